// round 10
// baseline (speedup 1.0000x reference)
#include <cuda_runtime.h>

// Problem constants (fixed by the dataset)
#define B_   64
#define C_   8
#define H_   256
#define W_   256
#define N_   200
#define NUM_CLASSES 3
#define NTGT (B_ * N_)                 // 12800
#define HW   (H_ * W_)                 // 65536

#define THREADS 256
#define BLOCKS  (NTGT / THREADS)       // 50 — best measured shape (MLP=8, 8 warps/SM)
#define NWARPS  (THREADS / 32)         // 8
#define TFLOATS (THREADS * 5)          // 1280 floats of targets per block
#define TVEC4   (TFLOATS / 4)          // 320 float4s

// Grid-wide accumulators: fp64 REDs (fire-and-forget, pipelined) + arrival
// counter; last block finalizes and resets -> deterministic under graph replay.
__device__ double g_acc[3];
__device__ unsigned int g_count;

__device__ __forceinline__ float softplus_f(float x) {
    // log(1+exp(x)) stable: max(x,0) + log1p(exp(-|x|))  (== jax.nn.softplus)
    return fmaxf(x, 0.0f) + log1pf(expf(-fabsf(x)));
}

__global__ void __launch_bounds__(THREADS)
yolo_loss_kernel(const float* __restrict__ pred,
                 const float* __restrict__ targets,
                 float* __restrict__ out)
{
    const int tid = threadIdx.x;

    // ---- stage this block's 1280 contiguous target floats into smem (float4) ----
    __shared__ float s_t[TFLOATS];
    {
        const float4* tg4 = (const float4*)(targets + (size_t)blockIdx.x * TFLOATS);
        float4* st4 = (float4*)s_t;
        st4[tid] = __ldg(tg4 + tid);                       // 256 float4s
        if (tid < TVEC4 - THREADS)                         // remaining 64
            st4[THREADS + tid] = __ldg(tg4 + THREADS + tid);
    }
    __syncthreads();

    float bbox_t = 0.0f, obj_t = 0.0f, cls_t = 0.0f;

    {
        // stride-5 smem reads: bank = (5*tid+j) % 32, 5 coprime 32 -> conflict-free
        const float cls_id = s_t[tid * 5 + 0];
        const float c0 = s_t[tid * 5 + 1], c1 = s_t[tid * 5 + 2];
        const float c2 = s_t[tid * 5 + 3], c3 = s_t[tid * 5 + 4];

        const int xpix = (int)(c0 * (float)W_);    // fp32 mul then trunc == astype(int32)
        const int ypix = (int)(c1 * (float)H_);

        // valid && in_bounds; when it holds, xpix/ypix are already in-range
        // so the reference's clip() is a no-op on live lanes.
        const bool live = (cls_id >= 0.0f) && ((c0 + c1 + c2 + c3) > 0.0f)
                        && (xpix >= 0) && (xpix < W_) && (ypix >= 0) && (ypix < H_);

        if (live) {
            const int g = blockIdx.x * THREADS + tid;      // target index
            const int b = g / N_;
            const float* base = pred + (size_t)b * (C_ * HW)
                                     + (size_t)(ypix << 8) + (size_t)xpix;

            // 8 independent scattered loads — MLP=8 hides DRAM latency
            float p[C_];
#pragma unroll
            for (int c = 0; c < C_; c++)
                p[c] = __ldg(base + (size_t)c * HW);

            // bbox: mean squared error over channels 0..3 vs coords
            const float d0 = p[0] - c0, d1 = p[1] - c1, d2 = p[2] - c2, d3 = p[3] - c3;
            bbox_t = 0.25f * (d0 * d0 + d1 * d1 + d2 * d2 + d3 * d3);

            // objectness: bce(p4, 1) = softplus(p4) - p4
            obj_t = softplus_f(p[4]) - p[4];

            // classification: mean over 3 classes of bce(p[5+j], onehot_j)
            const int k = (int)fmaxf(cls_id, 0.0f);
            float cs = 0.0f;
#pragma unroll
            for (int j = 0; j < NUM_CLASSES; j++) {
                const float lg = p[5 + j];
                cs += softplus_f(lg) - ((j == k) ? lg : 0.0f);
            }
            cls_t = cs * (1.0f / (float)NUM_CLASSES);
        }
    }

    // ---- block reduction (warp shuffles, then smem across 8 warps) ----
    const unsigned full = 0xFFFFFFFFu;
#pragma unroll
    for (int off = 16; off > 0; off >>= 1) {
        bbox_t += __shfl_down_sync(full, bbox_t, off);
        obj_t  += __shfl_down_sync(full, obj_t,  off);
        cls_t  += __shfl_down_sync(full, cls_t,  off);
    }

    __shared__ float s_b[NWARPS], s_o[NWARPS], s_c[NWARPS];
    const int warp = tid >> 5, lane = tid & 31;
    if (lane == 0) { s_b[warp] = bbox_t; s_o[warp] = obj_t; s_c[warp] = cls_t; }
    __syncthreads();

    __shared__ bool is_last;
    if (tid == 0) {
        float bb = 0.f, oo = 0.f, cc = 0.f;
#pragma unroll
        for (int w = 0; w < NWARPS; w++) { bb += s_b[w]; oo += s_o[w]; cc += s_c[w]; }

        atomicAdd(&g_acc[0], (double)bb);   // return unused -> RED, pipelined
        atomicAdd(&g_acc[1], (double)oo);
        atomicAdd(&g_acc[2], (double)cc);
        __threadfence();
        const unsigned v = atomicAdd(&g_count, 1u);
        is_last = (v == (unsigned)(BLOCKS - 1));
    }
    __syncthreads();

    // ---- last block finalizes and resets scratch for the next graph replay ----
    if (is_last && tid == 0) {
        __threadfence();   // observe all blocks' REDs
        const double bs = g_acc[0], os = g_acc[1], cs = g_acc[2];
        const double total = 0.05 * bs + 1.0 * os + 0.5 * cs;
        out[0] = (float)total;
        out[1] = (float)bs;
        out[2] = (float)os;
        out[3] = (float)cs;
        g_acc[0] = 0.0; g_acc[1] = 0.0; g_acc[2] = 0.0;
        g_count = 0u;
        __threadfence();
    }
}

extern "C" void kernel_launch(void* const* d_in, const int* in_sizes, int n_in,
                              void* d_out, int out_size)
{
    const float* pred    = (const float*)d_in[0];
    const float* targets = (const float*)d_in[1];
    float* out = (float*)d_out;
    (void)in_sizes; (void)n_in; (void)out_size;

    yolo_loss_kernel<<<BLOCKS, THREADS>>>(pred, targets, out);
}

// round 11
// speedup vs baseline: 1.2731x; 1.2731x over previous
#include <cuda_runtime.h>

// Problem constants (fixed by the dataset)
#define B_   64
#define C_   8
#define H_   256
#define W_   256
#define N_   200
#define NUM_CLASSES 3
#define NTGT (B_ * N_)                 // 12800
#define HW   (H_ * W_)                 // 65536

#define THREADS 256
#define BLOCKS  (NTGT / THREADS)       // 50 — best measured shape (MLP=8, 8 warps/SM)
#define NWARPS  (THREADS / 32)         // 8

// Grid-wide accumulators: fp64 REDs (fire-and-forget, pipelined) + arrival
// counter; last block finalizes and resets -> deterministic under graph replay.
__device__ double g_acc[3];
__device__ unsigned int g_count;

__device__ __forceinline__ float softplus_f(float x) {
    // log(1+exp(x)) stable: max(x,0) + log1p(exp(-|x|))  (== jax.nn.softplus)
    return fmaxf(x, 0.0f) + log1pf(expf(-fabsf(x)));
}

__global__ void __launch_bounds__(THREADS)
yolo_loss_kernel(const float* __restrict__ pred,
                 const float* __restrict__ targets,
                 float* __restrict__ out)
{
    const int tid = threadIdx.x;
    const int g   = blockIdx.x * THREADS + tid;    // target index (always < NTGT)

    float bbox_t = 0.0f, obj_t = 0.0f, cls_t = 0.0f;

    {
        // Direct strided loads — each warp proceeds independently (no barrier
        // between target reads and gathers; this beat smem staging).
        const float* t = targets + g * 5;
        const float cls_id = __ldg(t + 0);
        const float c0 = __ldg(t + 1), c1 = __ldg(t + 2);
        const float c2 = __ldg(t + 3), c3 = __ldg(t + 4);

        const int xpix = (int)(c0 * (float)W_);    // fp32 mul then trunc == astype(int32)
        const int ypix = (int)(c1 * (float)H_);

        // valid && in_bounds; when it holds, xpix/ypix are already in-range,
        // so the reference's clip() is a no-op on live lanes.
        const bool live = (cls_id >= 0.0f) && ((c0 + c1 + c2 + c3) > 0.0f)
                        && (xpix >= 0) && (xpix < W_) && (ypix >= 0) && (ypix < H_);

        if (live) {
            const int b = g / N_;                  // mulhi+shift
            const int off32 = b * (C_ * HW) + (ypix << 8) + xpix;   // fits in int32
            const float* base = pred + off32;

            // 8 independent scattered loads — MLP=8 hides DRAM latency
            float p[C_];
#pragma unroll
            for (int c = 0; c < C_; c++)
                p[c] = __ldg(base + c * HW);

            // bbox: mean squared error over channels 0..3 vs coords
            const float d0 = p[0] - c0, d1 = p[1] - c1, d2 = p[2] - c2, d3 = p[3] - c3;
            bbox_t = 0.25f * (d0 * d0 + d1 * d1 + d2 * d2 + d3 * d3);

            // objectness: bce(p4, 1) = softplus(p4) - p4
            obj_t = softplus_f(p[4]) - p[4];

            // classification: mean over 3 classes of bce(p[5+j], onehot_j)
            const int k = (int)fmaxf(cls_id, 0.0f);
            float cs = 0.0f;
#pragma unroll
            for (int j = 0; j < NUM_CLASSES; j++) {
                const float lg = p[5 + j];
                cs += softplus_f(lg) - ((j == k) ? lg : 0.0f);
            }
            cls_t = cs * (1.0f / (float)NUM_CLASSES);
        }
    }

    // ---- block reduction (warp shuffles, then smem across 8 warps) ----
    const unsigned full = 0xFFFFFFFFu;
#pragma unroll
    for (int off = 16; off > 0; off >>= 1) {
        bbox_t += __shfl_down_sync(full, bbox_t, off);
        obj_t  += __shfl_down_sync(full, obj_t,  off);
        cls_t  += __shfl_down_sync(full, cls_t,  off);
    }

    __shared__ float s_b[NWARPS], s_o[NWARPS], s_c[NWARPS];
    const int warp = tid >> 5, lane = tid & 31;
    if (lane == 0) { s_b[warp] = bbox_t; s_o[warp] = obj_t; s_c[warp] = cls_t; }
    __syncthreads();

    __shared__ bool is_last;
    if (tid == 0) {
        float bb = 0.f, oo = 0.f, cc = 0.f;
#pragma unroll
        for (int w = 0; w < NWARPS; w++) { bb += s_b[w]; oo += s_o[w]; cc += s_c[w]; }

        atomicAdd(&g_acc[0], (double)bb);   // return unused -> RED, pipelined
        atomicAdd(&g_acc[1], (double)oo);
        atomicAdd(&g_acc[2], (double)cc);
        __threadfence();
        const unsigned v = atomicAdd(&g_count, 1u);
        is_last = (v == (unsigned)(BLOCKS - 1));
    }
    __syncthreads();

    // ---- last block finalizes and resets scratch for the next graph replay ----
    if (is_last && tid == 0) {
        __threadfence();   // observe all blocks' REDs
        const double bs = g_acc[0], os = g_acc[1], cs = g_acc[2];
        const double total = 0.05 * bs + 1.0 * os + 0.5 * cs;
        out[0] = (float)total;
        out[1] = (float)bs;
        out[2] = (float)os;
        out[3] = (float)cs;
        g_acc[0] = 0.0; g_acc[1] = 0.0; g_acc[2] = 0.0;
        g_count = 0u;
        __threadfence();
    }
}

extern "C" void kernel_launch(void* const* d_in, const int* in_sizes, int n_in,
                              void* d_out, int out_size)
{
    const float* pred    = (const float*)d_in[0];
    const float* targets = (const float*)d_in[1];
    float* out = (float*)d_out;
    (void)in_sizes; (void)n_in; (void)out_size;

    yolo_loss_kernel<<<BLOCKS, THREADS>>>(pred, targets, out);
}